// round 1
// baseline (speedup 1.0000x reference)
#include <cuda_runtime.h>
#include <cstdint>
#include <cstddef>

// ---------------- problem constants ----------------
#define Hn      1024
#define En      512
#define AEn     576
#define SEQn    64
#define NSTEPn  128
#define NBLKn   128
#define UPBn    8      // hidden units per block   (128*8 = 1024)
#define RPBn    32     // gate rows per block      (8 units * 4 gates)
#define NTHRn   512
#define VOCABn  50257

// ---------------- global scratch (no allocations allowed) ----------------
__device__ float    g_h[Hn];
__device__ float    g_hs[SEQn * Hn];
__device__ float    g_logits[SEQn * VOCABn];
__device__ unsigned g_bar_count;
__device__ unsigned g_bar_phase;

// =====================================================================
// Persistent LSTM kernel: 128 CTAs, each owns 8 hidden units.
//  Phase A: precompute Gx[t][row] = x_t . Wih[row] + bih + bhh for all 128 steps (local, no syncs)
//  Phase B: 128 timesteps, grid barrier per step, Whh slice resident in SMEM.
// =====================================================================
__global__ void __launch_bounds__(NTHRn, 1)
lstm_kernel(const int* __restrict__ in_seq, const float* __restrict__ feats,
            const int* __restrict__ dec_seq, const float* __restrict__ emb,
            const float* __restrict__ eWih, const float* __restrict__ eWhh,
            const float* __restrict__ ebih, const float* __restrict__ ebhh,
            const float* __restrict__ dWih, const float* __restrict__ dWhh,
            const float* __restrict__ dbih, const float* __restrict__ dbhh)
{
    extern __shared__ float sm[];
    float* w_s     = sm;                         // 32768 floats (32 rows x 1024)
    float* gx_s    = w_s + RPBn * Hn;            // 4096 floats  (128 steps x 32 rows)
    float* h_s     = gx_s + NSTEPn * RPBn;       // 1024
    float* x_s     = h_s + Hn;                   // 576
    float* gates_s = x_s + AEn;                  // 32
    float* c_s     = gates_s + RPBn;             // 8
    unsigned* base_s = (unsigned*)(c_s + UPBn);  // 1

    const int tid  = threadIdx.x;
    const int lane = tid & 31;
    const int wid  = tid >> 5;
    const int blk  = blockIdx.x;

    if (tid == 0) base_s[0] = *(volatile unsigned*)&g_bar_phase;
    if (tid < UPBn) c_s[tid] = 0.f;
    for (int i = tid; i < Hn; i += NTHRn) h_s[i] = 0.f;

    // each warp handles two local gate rows: r_local = q*4 + gate
    const int r0 = 2 * wid, r1 = r0 + 1;
    const int grow0 = ((r0 & 3) << 10) + blk * UPBn + (r0 >> 2);
    const int grow1 = ((r1 & 3) << 10) + blk * UPBn + (r1 >> 2);

    // ---------------- Phase A1: encoder Gx ----------------
    {
        float4* dst = (float4*)w_s;
        for (int idx = tid; idx < RPBn * 128; idx += NTHRn) {   // 512 floats/row = 128 float4
            int r = idx >> 7, c4 = idx & 127;
            int gr = ((r & 3) << 10) + blk * UPBn + (r >> 2);
            dst[r * 128 + c4] = ((const float4*)eWih)[gr * 128 + c4];
        }
        float b0 = ebih[grow0] + ebhh[grow0];
        float b1 = ebih[grow1] + ebhh[grow1];
        const float4* w0 = (const float4*)(w_s + r0 * En);
        const float4* w1 = (const float4*)(w_s + r1 * En);
        for (int t = 0; t < SEQn; t++) {
            int tok = in_seq[t];
            for (int i = tid; i < En; i += NTHRn) x_s[i] = emb[(size_t)tok * En + i];
            __syncthreads();
            const float4* xp = (const float4*)x_s;
            float a0 = 0.f, a1 = 0.f;
            #pragma unroll
            for (int k = 0; k < 4; k++) {
                int idx = k * 32 + lane;
                float4 xv = xp[idx];
                float4 v0 = w0[idx];
                float4 v1 = w1[idx];
                a0 = fmaf(xv.x, v0.x, fmaf(xv.y, v0.y, fmaf(xv.z, v0.z, fmaf(xv.w, v0.w, a0))));
                a1 = fmaf(xv.x, v1.x, fmaf(xv.y, v1.y, fmaf(xv.z, v1.z, fmaf(xv.w, v1.w, a1))));
            }
            #pragma unroll
            for (int o = 16; o; o >>= 1) {
                a0 += __shfl_xor_sync(0xffffffffu, a0, o);
                a1 += __shfl_xor_sync(0xffffffffu, a1, o);
            }
            if (lane == 0) { gx_s[t * RPBn + r0] = a0 + b0; gx_s[t * RPBn + r1] = a1 + b1; }
            __syncthreads();
        }
    }

    // ---------------- Phase A2: decoder Gx ----------------
    {
        float4* dst = (float4*)w_s;
        for (int idx = tid; idx < RPBn * 144; idx += NTHRn) {   // 576 floats/row = 144 float4
            int r = idx / 144, c4 = idx % 144;
            int gr = ((r & 3) << 10) + blk * UPBn + (r >> 2);
            dst[r * 144 + c4] = ((const float4*)dWih)[gr * 144 + c4];
        }
        float b0 = dbih[grow0] + dbhh[grow0];
        float b1 = dbih[grow1] + dbhh[grow1];
        const float4* w0 = (const float4*)(w_s + r0 * AEn);
        const float4* w1 = (const float4*)(w_s + r1 * AEn);
        for (int t = 0; t < SEQn; t++) {
            int tok = dec_seq[t];
            for (int i = tid; i < En; i += NTHRn) x_s[i] = emb[(size_t)tok * En + i];
            if (tid < AEn - En) x_s[En + tid] = feats[tid];
            __syncthreads();
            const float4* xp = (const float4*)x_s;
            float a0 = 0.f, a1 = 0.f;
            #pragma unroll
            for (int k = 0; k < 5; k++) {
                int idx = k * 32 + lane;
                if (idx < 144) {
                    float4 xv = xp[idx];
                    float4 v0 = w0[idx];
                    float4 v1 = w1[idx];
                    a0 = fmaf(xv.x, v0.x, fmaf(xv.y, v0.y, fmaf(xv.z, v0.z, fmaf(xv.w, v0.w, a0))));
                    a1 = fmaf(xv.x, v1.x, fmaf(xv.y, v1.y, fmaf(xv.z, v1.z, fmaf(xv.w, v1.w, a1))));
                }
            }
            #pragma unroll
            for (int o = 16; o; o >>= 1) {
                a0 += __shfl_xor_sync(0xffffffffu, a0, o);
                a1 += __shfl_xor_sync(0xffffffffu, a1, o);
            }
            if (lane == 0) {
                gx_s[(SEQn + t) * RPBn + r0] = a0 + b0;
                gx_s[(SEQn + t) * RPBn + r1] = a1 + b1;
            }
            __syncthreads();
        }
    }

    // ---------------- Phase B: recurrent loop ----------------
    {
        float4* dst = (float4*)w_s;
        for (int idx = tid; idx < RPBn * 256; idx += NTHRn) {   // 1024 floats/row = 256 float4
            int r = idx >> 8, c4 = idx & 255;
            int gr = ((r & 3) << 10) + blk * UPBn + (r >> 2);
            dst[r * 256 + c4] = ((const float4*)eWhh)[gr * 256 + c4];
        }
    }
    __syncthreads();
    const unsigned base = base_s[0];

    const float4* wr0 = (const float4*)(w_s + r0 * Hn);
    const float4* wr1 = (const float4*)(w_s + r1 * Hn);

    for (int t = 0; t < NSTEPn; t++) {
        if (t == SEQn) {
            // swap in decoder Whh slice (everyone is past all reads of enc slice)
            float4* dst = (float4*)w_s;
            for (int idx = tid; idx < RPBn * 256; idx += NTHRn) {
                int r = idx >> 8, c4 = idx & 255;
                int gr = ((r & 3) << 10) + blk * UPBn + (r >> 2);
                dst[r * 256 + c4] = ((const float4*)dWhh)[gr * 256 + c4];
            }
            __syncthreads();
        }

        const float4* hp = (const float4*)h_s;
        float a0 = 0.f, a1 = 0.f;
        #pragma unroll
        for (int k = 0; k < 8; k++) {
            int idx = k * 32 + lane;
            float4 hv = hp[idx];
            float4 v0 = wr0[idx];
            float4 v1 = wr1[idx];
            a0 = fmaf(hv.x, v0.x, fmaf(hv.y, v0.y, fmaf(hv.z, v0.z, fmaf(hv.w, v0.w, a0))));
            a1 = fmaf(hv.x, v1.x, fmaf(hv.y, v1.y, fmaf(hv.z, v1.z, fmaf(hv.w, v1.w, a1))));
        }
        #pragma unroll
        for (int o = 16; o; o >>= 1) {
            a0 += __shfl_xor_sync(0xffffffffu, a0, o);
            a1 += __shfl_xor_sync(0xffffffffu, a1, o);
        }
        if (lane == 0) {
            gates_s[r0] = a0 + gx_s[t * RPBn + r0];
            gates_s[r1] = a1 + gx_s[t * RPBn + r1];
        }
        __syncthreads();

        if (tid < UPBn) {
            int q = tid;
            float gi = gates_s[q * 4 + 0];
            float gf = gates_s[q * 4 + 1];
            float gg = gates_s[q * 4 + 2];
            float go = gates_s[q * 4 + 3];
            float si = 1.f / (1.f + expf(-gi));
            float sf = 1.f / (1.f + expf(-gf));
            float so = 1.f / (1.f + expf(-go));
            float c  = fmaf(sf, c_s[q], si * tanhf(gg));
            float hv = so * tanhf(c);
            c_s[q] = c;
            int unit = blk * UPBn + q;
            g_h[unit] = hv;
            if (t >= SEQn) g_hs[(t - SEQn) * Hn + unit] = hv;
        }

        // ---- grid barrier (phase-monotonic, replay-safe) ----
        __syncthreads();
        if (tid == 0) {
            __threadfence();
            unsigned target = base + (unsigned)t + 1u;
            unsigned old = atomicAdd(&g_bar_count, 1u);
            if (old == NBLKn - 1) {
                g_bar_count = 0;
                __threadfence();
                atomicExch(&g_bar_phase, target);
            } else {
                while ((int)(*(volatile unsigned*)&g_bar_phase - target) < 0) __nanosleep(32);
                __threadfence();
            }
        }
        __syncthreads();

        // stage the fresh h for next step (bypass L1, it may hold stale lines)
        for (int i = tid; i < Hn; i += NTHRn) h_s[i] = __ldcg(&g_h[i]);
        __syncthreads();
    }
}

// =====================================================================
// Output GEMM: logits[64, 50257] = hs[64,1024] @ linW[50257,1024]^T + b
// Register-tiled fp32: BM=64, BN=128, BK=16, 128 threads, 8x8 micro-tile.
// =====================================================================
#define GBN 128
#define GBK 16
#define AS_LD 68
#define BS_LD 132

__global__ void __launch_bounds__(128)
gemm_kernel(const float* __restrict__ linW, const float* __restrict__ linb)
{
    __shared__ float As[GBK * AS_LD];   // [k][m], padded
    __shared__ float Bs[GBK * BS_LD];   // [k][n], padded

    const int tid = threadIdx.x;
    const int n0  = blockIdx.x * GBN;
    const int tx  = tid & 15;   // n sub-tile (8 each -> 128)
    const int ty  = tid >> 4;   // m sub-tile (8 each -> 64)

    float acc[8][8];
    #pragma unroll
    for (int i = 0; i < 8; i++)
        #pragma unroll
        for (int j = 0; j < 8; j++) acc[i][j] = 0.f;

    for (int k0 = 0; k0 < Hn; k0 += GBK) {
        // load A tile (hs): 64 m x 16 k = 256 float4, 2 per thread, transpose to [k][m]
        #pragma unroll
        for (int i = 0; i < 2; i++) {
            int idx = tid + i * 128;
            int m = idx >> 2, k4 = idx & 3;
            float4 v = *(const float4*)&g_hs[m * Hn + k0 + k4 * 4];
            As[(k4 * 4 + 0) * AS_LD + m] = v.x;
            As[(k4 * 4 + 1) * AS_LD + m] = v.y;
            As[(k4 * 4 + 2) * AS_LD + m] = v.z;
            As[(k4 * 4 + 3) * AS_LD + m] = v.w;
        }
        // load B tile (linW rows): 128 n x 16 k = 512 float4, 4 per thread
        #pragma unroll
        for (int i = 0; i < 4; i++) {
            int idx = tid + i * 128;
            int n = idx >> 2, k4 = idx & 3;
            int gn = n0 + n;
            float4 v = make_float4(0.f, 0.f, 0.f, 0.f);
            if (gn < VOCABn) v = *(const float4*)&linW[(size_t)gn * Hn + k0 + k4 * 4];
            Bs[(k4 * 4 + 0) * BS_LD + n] = v.x;
            Bs[(k4 * 4 + 1) * BS_LD + n] = v.y;
            Bs[(k4 * 4 + 2) * BS_LD + n] = v.z;
            Bs[(k4 * 4 + 3) * BS_LD + n] = v.w;
        }
        __syncthreads();

        #pragma unroll
        for (int k = 0; k < GBK; k++) {
            float4 a0 = *(const float4*)&As[k * AS_LD + ty * 8];
            float4 a1 = *(const float4*)&As[k * AS_LD + ty * 8 + 4];
            float4 b0 = *(const float4*)&Bs[k * BS_LD + tx * 8];
            float4 b1 = *(const float4*)&Bs[k * BS_LD + tx * 8 + 4];
            float a[8] = {a0.x, a0.y, a0.z, a0.w, a1.x, a1.y, a1.z, a1.w};
            float b[8] = {b0.x, b0.y, b0.z, b0.w, b1.x, b1.y, b1.z, b1.w};
            #pragma unroll
            for (int i = 0; i < 8; i++)
                #pragma unroll
                for (int j = 0; j < 8; j++)
                    acc[i][j] = fmaf(a[i], b[j], acc[i][j]);
        }
        __syncthreads();
    }

    #pragma unroll
    for (int i = 0; i < 8; i++) {
        int m = ty * 8 + i;
        #pragma unroll
        for (int j = 0; j < 8; j++) {
            int gn = n0 + tx * 8 + j;
            if (gn < VOCABn)
                g_logits[(size_t)m * VOCABn + gn] = acc[i][j] + linb[gn];
        }
    }
}

// =====================================================================
// Fused relu + log_softmax per decoder step, one block per row.
// =====================================================================
__global__ void __launch_bounds__(512)
softmax_kernel(float* __restrict__ out)
{
    __shared__ float red[16];
    const int t = blockIdx.x;
    const float* row = g_logits + (size_t)t * VOCABn;
    const int tid = threadIdx.x, lane = tid & 31, wid = tid >> 5;

    // max over relu(logits); relu floor handled by init = 0
    float m = 0.f;
    for (int i = tid; i < VOCABn; i += 512) m = fmaxf(m, row[i]);
    #pragma unroll
    for (int o = 16; o; o >>= 1) m = fmaxf(m, __shfl_xor_sync(0xffffffffu, m, o));
    if (lane == 0) red[wid] = m;
    __syncthreads();
    if (tid < 16) {
        float v = red[tid];
        #pragma unroll
        for (int o = 8; o; o >>= 1) v = fmaxf(v, __shfl_xor_sync(0x0000ffffu, v, o));
        if (tid == 0) red[0] = v;
    }
    __syncthreads();
    m = red[0];
    __syncthreads();

    float s = 0.f;
    for (int i = tid; i < VOCABn; i += 512) s += expf(fmaxf(row[i], 0.f) - m);
    #pragma unroll
    for (int o = 16; o; o >>= 1) s += __shfl_xor_sync(0xffffffffu, s, o);
    if (lane == 0) red[wid] = s;
    __syncthreads();
    if (tid < 16) {
        float v = red[tid];
        #pragma unroll
        for (int o = 8; o; o >>= 1) v += __shfl_xor_sync(0x0000ffffu, v, o);
        if (tid == 0) red[0] = v;
    }
    __syncthreads();
    const float lse = m + logf(red[0]);

    float* orow = out + (size_t)t * VOCABn;
    for (int i = tid; i < VOCABn; i += 512) orow[i] = fmaxf(row[i], 0.f) - lse;
}

// =====================================================================
extern "C" void kernel_launch(void* const* d_in, const int* in_sizes, int n_in,
                              void* d_out, int out_size)
{
    const int*   in_seq  = (const int*)d_in[0];
    const float* feats   = (const float*)d_in[1];
    const int*   dec_seq = (const int*)d_in[2];
    const float* emb     = (const float*)d_in[3];
    const float* eWih    = (const float*)d_in[4];
    const float* eWhh    = (const float*)d_in[5];
    const float* ebih    = (const float*)d_in[6];
    const float* ebhh    = (const float*)d_in[7];
    const float* dWih    = (const float*)d_in[8];
    const float* dWhh    = (const float*)d_in[9];
    const float* dbih    = (const float*)d_in[10];
    const float* dbhh    = (const float*)d_in[11];
    const float* linW    = (const float*)d_in[12];
    const float* linb    = (const float*)d_in[13];

    const size_t smem_bytes =
        (size_t)(RPBn * Hn + NSTEPn * RPBn + Hn + AEn + RPBn + UPBn + 4) * sizeof(float);

    cudaFuncSetAttribute(lstm_kernel, cudaFuncAttributeMaxDynamicSharedMemorySize,
                         (int)smem_bytes);

    lstm_kernel<<<NBLKn, NTHRn, smem_bytes>>>(in_seq, feats, dec_seq, emb,
                                              eWih, eWhh, ebih, ebhh,
                                              dWih, dWhh, dbih, dbhh);
    gemm_kernel<<<(VOCABn + GBN - 1) / GBN, 128>>>(linW, linb);
    softmax_kernel<<<SEQn, 512>>>((float*)d_out);
}

// round 3
// speedup vs baseline: 1.0971x; 1.0971x over previous
#include <cuda_runtime.h>
#include <cstdint>
#include <cstddef>

// ---------------- problem constants ----------------
#define Hn      1024
#define En      512
#define AEn     576
#define SEQn    64
#define NSTEPn  128
#define NBLKn   128
#define UPBn    8      // hidden units per block   (128*8 = 1024)
#define RPBn    32     // gate rows per block      (8 units * 4 gates)
#define NTHRn   512
#define VOCABn  50257

// ---------------- global scratch (no allocations allowed) ----------------
__device__ float    g_hbuf[2][Hn];          // double-buffered h broadcast
__device__ float    g_hs[SEQn * Hn];        // decoder hidden states
__device__ float    g_logits[SEQn * VOCABn];
__device__ unsigned g_epoch[NBLKn * 8];     // per-CTA epoch flags, 32B apart

// =====================================================================
// Persistent LSTM kernel: 128 CTAs, each owns 8 hidden units.
//  Phase A: precompute Gx[t][row] = x_t . Wih[row] + biases (local, x double-buffered)
//  Phase B: 128 timesteps synced via per-CTA epoch flags (no atomics, no
//           central release broadcast) + per-producer 32B h gather.
// =====================================================================
__global__ void __launch_bounds__(NTHRn, 1)
lstm_kernel(const int* __restrict__ in_seq, const float* __restrict__ feats,
            const int* __restrict__ dec_seq, const float* __restrict__ emb,
            const float* __restrict__ eWih, const float* __restrict__ eWhh,
            const float* __restrict__ ebih, const float* __restrict__ ebhh,
            const float* __restrict__ dWih, const float* __restrict__ dWhh,
            const float* __restrict__ dbih, const float* __restrict__ dbhh)
{
    extern __shared__ float sm[];
    float* w_s     = sm;                          // 32768 floats (32 rows x 1024)
    float* gx_s    = w_s + RPBn * Hn;             // 4096 floats (128 steps x 32 rows)
    float* h_s     = gx_s + NSTEPn * RPBn;        // 1024
    float* x_s     = h_s + Hn;                    // 2 x 576 (double buffer)
    float* gates_s = x_s + 2 * AEn;               // 32
    float* c_s     = gates_s + RPBn;              // 8
    unsigned* base_s = (unsigned*)(c_s + UPBn);   // 1

    const int tid  = threadIdx.x;
    const int lane = tid & 31;
    const int wid  = tid >> 5;
    const int blk  = blockIdx.x;

    if (tid == 0) base_s[0] = *(volatile unsigned*)&g_epoch[blk * 8];
    if (tid < UPBn) c_s[tid] = 0.f;
    for (int i = tid; i < Hn; i += NTHRn) h_s[i] = 0.f;

    // each warp handles two local gate rows: r_local = q*4 + gate
    const int r0 = 2 * wid, r1 = r0 + 1;
    const int grow0 = ((r0 & 3) << 10) + blk * UPBn + (r0 >> 2);
    const int grow1 = ((r1 & 3) << 10) + blk * UPBn + (r1 >> 2);

    // ---------------- Phase A1: encoder Gx (x double-buffered) ----------------
    {
        float4* dst = (float4*)w_s;
        for (int idx = tid; idx < RPBn * 128; idx += NTHRn) {   // 512 floats/row = 128 float4
            int r = idx >> 7, c4 = idx & 127;
            int gr = ((r & 3) << 10) + blk * UPBn + (r >> 2);
            dst[r * 128 + c4] = ((const float4*)eWih)[gr * 128 + c4];
        }
        float b0 = ebih[grow0] + ebhh[grow0];
        float b1 = ebih[grow1] + ebhh[grow1];
        const int tok0 = in_seq[0];
        x_s[tid] = emb[(size_t)tok0 * En + tid];
        __syncthreads();

        for (int t = 0; t < SEQn; t++) {
            const float* xc = x_s + (t & 1) * AEn;
            float* xn = x_s + ((t + 1) & 1) * AEn;
            float xnext = 0.f;
            const bool has = (t + 1 < SEQn);
            if (has) xnext = emb[(size_t)in_seq[t + 1] * En + tid];

            const float4* w0 = (const float4*)(w_s + r0 * En);
            const float4* w1 = (const float4*)(w_s + r1 * En);
            const float4* xp = (const float4*)xc;
            float a0 = 0.f, a1 = 0.f;
            #pragma unroll
            for (int k = 0; k < 4; k++) {
                int idx = k * 32 + lane;
                float4 xv = xp[idx];
                float4 v0 = w0[idx];
                float4 v1 = w1[idx];
                a0 = fmaf(xv.x, v0.x, fmaf(xv.y, v0.y, fmaf(xv.z, v0.z, fmaf(xv.w, v0.w, a0))));
                a1 = fmaf(xv.x, v1.x, fmaf(xv.y, v1.y, fmaf(xv.z, v1.z, fmaf(xv.w, v1.w, a1))));
            }
            #pragma unroll
            for (int o = 16; o; o >>= 1) {
                a0 += __shfl_xor_sync(0xffffffffu, a0, o);
                a1 += __shfl_xor_sync(0xffffffffu, a1, o);
            }
            if (lane == 0) { gx_s[t * RPBn + r0] = a0 + b0; gx_s[t * RPBn + r1] = a1 + b1; }
            if (has) xn[tid] = xnext;
            __syncthreads();
        }
    }

    // ---------------- Phase A2: decoder Gx ----------------
    {
        float4* dst = (float4*)w_s;
        for (int idx = tid; idx < RPBn * 144; idx += NTHRn) {   // 576 floats/row = 144 float4
            int r = idx / 144, c4 = idx % 144;
            int gr = ((r & 3) << 10) + blk * UPBn + (r >> 2);
            dst[r * 144 + c4] = ((const float4*)dWih)[gr * 144 + c4];
        }
        float b0 = dbih[grow0] + dbhh[grow0];
        float b1 = dbih[grow1] + dbhh[grow1];
        // feats tail: constant across steps -> preload both buffers
        if (tid < AEn - En) {
            float fv = feats[tid];
            x_s[En + tid] = fv;
            x_s[AEn + En + tid] = fv;
        }
        const int tok0 = dec_seq[0];
        x_s[tid] = emb[(size_t)tok0 * En + tid];
        __syncthreads();

        for (int t = 0; t < SEQn; t++) {
            const float* xc = x_s + (t & 1) * AEn;
            float* xn = x_s + ((t + 1) & 1) * AEn;
            float xnext = 0.f;
            const bool has = (t + 1 < SEQn);
            if (has) xnext = emb[(size_t)dec_seq[t + 1] * En + tid];

            const float4* w0 = (const float4*)(w_s + r0 * AEn);
            const float4* w1 = (const float4*)(w_s + r1 * AEn);
            const float4* xp = (const float4*)xc;
            float a0 = 0.f, a1 = 0.f;
            #pragma unroll
            for (int k = 0; k < 5; k++) {
                int idx = k * 32 + lane;
                if (idx < 144) {
                    float4 xv = xp[idx];
                    float4 v0 = w0[idx];
                    float4 v1 = w1[idx];
                    a0 = fmaf(xv.x, v0.x, fmaf(xv.y, v0.y, fmaf(xv.z, v0.z, fmaf(xv.w, v0.w, a0))));
                    a1 = fmaf(xv.x, v1.x, fmaf(xv.y, v1.y, fmaf(xv.z, v1.z, fmaf(xv.w, v1.w, a1))));
                }
            }
            #pragma unroll
            for (int o = 16; o; o >>= 1) {
                a0 += __shfl_xor_sync(0xffffffffu, a0, o);
                a1 += __shfl_xor_sync(0xffffffffu, a1, o);
            }
            if (lane == 0) {
                gx_s[(SEQn + t) * RPBn + r0] = a0 + b0;
                gx_s[(SEQn + t) * RPBn + r1] = a1 + b1;
            }
            if (has) xn[tid] = xnext;
            __syncthreads();
        }
    }

    // ---------------- Phase B: recurrent loop ----------------
    {
        float4* dst = (float4*)w_s;
        for (int idx = tid; idx < RPBn * 256; idx += NTHRn) {   // 1024 floats/row = 256 float4
            int r = idx >> 8, c4 = idx & 255;
            int gr = ((r & 3) << 10) + blk * UPBn + (r >> 2);
            dst[r * 256 + c4] = ((const float4*)eWhh)[gr * 256 + c4];
        }
    }
    __syncthreads();
    const unsigned base = base_s[0];

    const float4* wr0 = (const float4*)(w_s + r0 * Hn);
    const float4* wr1 = (const float4*)(w_s + r1 * Hn);

    for (int t = 0; t < NSTEPn; t++) {
        if (t == SEQn) {
            // swap in decoder Whh slice (all reads of enc slice are done)
            float4* dst = (float4*)w_s;
            for (int idx = tid; idx < RPBn * 256; idx += NTHRn) {
                int r = idx >> 8, c4 = idx & 255;
                int gr = ((r & 3) << 10) + blk * UPBn + (r >> 2);
                dst[r * 256 + c4] = ((const float4*)dWhh)[gr * 256 + c4];
            }
            __syncthreads();
        }

        // ---- Whh . h (each warp: 2 gate rows) ----
        const float4* hp = (const float4*)h_s;
        float a0 = 0.f, a1 = 0.f;
        #pragma unroll
        for (int k = 0; k < 8; k++) {
            int idx = k * 32 + lane;
            float4 hv4 = hp[idx];
            float4 v0 = wr0[idx];
            float4 v1 = wr1[idx];
            a0 = fmaf(hv4.x, v0.x, fmaf(hv4.y, v0.y, fmaf(hv4.z, v0.z, fmaf(hv4.w, v0.w, a0))));
            a1 = fmaf(hv4.x, v1.x, fmaf(hv4.y, v1.y, fmaf(hv4.z, v1.z, fmaf(hv4.w, v1.w, a1))));
        }
        #pragma unroll
        for (int o = 16; o; o >>= 1) {
            a0 += __shfl_xor_sync(0xffffffffu, a0, o);
            a1 += __shfl_xor_sync(0xffffffffu, a1, o);
        }
        if (lane == 0) {
            gates_s[r0] = a0 + gx_s[t * RPBn + r0];
            gates_s[r1] = a1 + gx_s[t * RPBn + r1];
        }
        __syncthreads();   // (S1) gates ready; all h_s reads for this step done

        // ---- gate nonlinearity + publish (warp 0) ----
        float hv = 0.f;
        if (tid < UPBn) {
            int q = tid;
            float gi = gates_s[q * 4 + 0];
            float gf = gates_s[q * 4 + 1];
            float gg = gates_s[q * 4 + 2];
            float go = gates_s[q * 4 + 3];
            float si = 1.f / (1.f + expf(-gi));
            float sf = 1.f / (1.f + expf(-gf));
            float so = 1.f / (1.f + expf(-go));
            float c  = fmaf(sf, c_s[q], si * tanhf(gg));
            hv = so * tanhf(c);
            c_s[q] = c;
            if (t >= SEQn) g_hs[(t - SEQn) * Hn + blk * UPBn + q] = hv;
        }
        if (wid == 0) {
            float v0 = __shfl_sync(0xffffffffu, hv, 0);
            float v1 = __shfl_sync(0xffffffffu, hv, 1);
            float v2 = __shfl_sync(0xffffffffu, hv, 2);
            float v3 = __shfl_sync(0xffffffffu, hv, 3);
            float v4 = __shfl_sync(0xffffffffu, hv, 4);
            float v5 = __shfl_sync(0xffffffffu, hv, 5);
            float v6 = __shfl_sync(0xffffffffu, hv, 6);
            float v7 = __shfl_sync(0xffffffffu, hv, 7);
            if (lane == 0) {
                float4* dp = (float4*)&g_hbuf[t & 1][blk * UPBn];
                __stcg(dp,     make_float4(v0, v1, v2, v3));
                __stcg(dp + 1, make_float4(v4, v5, v6, v7));
                __threadfence();
                *(volatile unsigned*)&g_epoch[blk * 8] = base + (unsigned)t + 1u;
            }
        }

        // ---- consumers: one thread per producer CTA, no atomics ----
        if (tid < NBLKn) {
            const unsigned target = base + (unsigned)t + 1u;
            const volatile unsigned* ep = &g_epoch[tid * 8];
            if ((int)(*ep - target) < 0) {
                while ((int)(*ep - target) < 0) __nanosleep(20);
            }
            __threadfence();   // acquire
            float4 lo = __ldcg((const float4*)&g_hbuf[t & 1][tid * UPBn]);
            float4 hi = __ldcg((const float4*)&g_hbuf[t & 1][tid * UPBn + 4]);
            float4* hdst = (float4*)&h_s[tid * UPBn];
            hdst[0] = lo;
            hdst[1] = hi;
        }
        __syncthreads();   // (S2) h_s holds h_{t+1}
    }
}

// =====================================================================
// Output GEMM via tf32 tensor cores:
//   logits[64, 50257] = hs[64,1024] @ linW[50257,1024]^T + b
// BM=64, BN=128, BK=32, 256 threads (8 warps, 2m x 4n), 2-stage cp.async.
// =====================================================================
#define GBM 64
#define GBN 128
#define GBK 32
#define LDT 40                       // padded floats per smem row
#define A_STAGE (GBM * LDT)          // 2560 floats
#define B_STAGE (GBN * LDT)          // 5120 floats
#define STAGEF  (A_STAGE + B_STAGE)  // 7680 floats
#define GEMM_SMEM (2 * STAGEF * 4)   // 61440 bytes

__device__ __forceinline__ void cp_async16(float* smem_dst, const void* gsrc) {
    uint32_t d = (uint32_t)__cvta_generic_to_shared(smem_dst);
    asm volatile("cp.async.cg.shared.global [%0], [%1], 16;\n" :: "r"(d), "l"(gsrc));
}
__device__ __forceinline__ void cp_async16z(float* smem_dst, const void* gsrc, int szbytes) {
    uint32_t d = (uint32_t)__cvta_generic_to_shared(smem_dst);
    asm volatile("cp.async.cg.shared.global [%0], [%1], 16, %2;\n" :: "r"(d), "l"(gsrc), "r"(szbytes));
}

__global__ void __launch_bounds__(256, 2)
gemm_kernel(const float* __restrict__ linW, const float* __restrict__ linb)
{
    extern __shared__ float smg[];
    const int tid  = threadIdx.x;
    const int n0   = blockIdx.x * GBN;
    const int warp = tid >> 5, lane = tid & 31;
    const int wm   = warp >> 2, wn = warp & 3;
    const int g    = lane >> 2, tg = lane & 3;

    float acc[2][4][4];
    #pragma unroll
    for (int i = 0; i < 2; i++)
        #pragma unroll
        for (int j = 0; j < 4; j++)
            #pragma unroll
            for (int k = 0; k < 4; k++) acc[i][j][k] = 0.f;

    // stage loader: A (64x32) + B (128x32), coalesced 16B cp.async
    auto issue_stage = [&](int k0, int s) {
        float* As = smg + s * STAGEF;
        float* Bs = As + A_STAGE;
        #pragma unroll
        for (int i = 0; i < 2; i++) {
            int idx = i * 256 + tid;
            int m = idx >> 3, kq = idx & 7;
            cp_async16(&As[m * LDT + kq * 4], &g_hs[m * Hn + k0 + kq * 4]);
        }
        #pragma unroll
        for (int i = 0; i < 4; i++) {
            int idx = i * 256 + tid;
            int n = idx >> 3, kq = idx & 7;
            int gn = n0 + n;
            int cgn = (gn < VOCABn) ? gn : (VOCABn - 1);
            int sz  = (gn < VOCABn) ? 16 : 0;
            cp_async16z(&Bs[n * LDT + kq * 4], &linW[(size_t)cgn * Hn + k0 + kq * 4], sz);
        }
        asm volatile("cp.async.commit_group;\n");
    };

    issue_stage(0, 0);
    const int NCH = Hn / GBK;   // 32
    for (int c = 0; c < NCH; c++) {
        int s = c & 1;
        if (c + 1 < NCH) {
            issue_stage((c + 1) * GBK, s ^ 1);
            asm volatile("cp.async.wait_group 1;\n");
        } else {
            asm volatile("cp.async.wait_group 0;\n");
        }
        __syncthreads();

        const float* As = smg + s * STAGEF;
        const float* Bs = As + A_STAGE;
        #pragma unroll
        for (int ks = 0; ks < 4; ks++) {
            const int kk = ks * 8;
            uint32_t a[2][4], b[4][2];
            #pragma unroll
            for (int mt = 0; mt < 2; mt++) {
                const float* ap = &As[(wm * 32 + mt * 16 + g) * LDT + kk + tg];
                a[mt][0] = __float_as_uint(ap[0]);
                a[mt][1] = __float_as_uint(ap[8 * LDT]);
                a[mt][2] = __float_as_uint(ap[4]);
                a[mt][3] = __float_as_uint(ap[8 * LDT + 4]);
            }
            #pragma unroll
            for (int nt = 0; nt < 4; nt++) {
                const float* bp = &Bs[(wn * 32 + nt * 8 + g) * LDT + kk + tg];
                b[nt][0] = __float_as_uint(bp[0]);
                b[nt][1] = __float_as_uint(bp[4]);
            }
            #pragma unroll
            for (int mt = 0; mt < 2; mt++)
                #pragma unroll
                for (int nt = 0; nt < 4; nt++) {
                    asm volatile(
                        "mma.sync.aligned.m16n8k8.row.col.f32.tf32.tf32.f32 "
                        "{%0,%1,%2,%3}, {%4,%5,%6,%7}, {%8,%9}, {%0,%1,%2,%3};\n"
                        : "+f"(acc[mt][nt][0]), "+f"(acc[mt][nt][1]),
                          "+f"(acc[mt][nt][2]), "+f"(acc[mt][nt][3])
                        : "r"(a[mt][0]), "r"(a[mt][1]), "r"(a[mt][2]), "r"(a[mt][3]),
                          "r"(b[nt][0]), "r"(b[nt][1]));
                }
        }
        __syncthreads();
    }

    // epilogue: add bias, write logits (scalar stores, rows have odd stride)
    #pragma unroll
    for (int mt = 0; mt < 2; mt++) {
        const int m0 = wm * 32 + mt * 16 + g;
        #pragma unroll
        for (int nt = 0; nt < 4; nt++) {
            const int cn = n0 + wn * 32 + nt * 8 + 2 * tg;
            if (cn < VOCABn) {
                float bb = linb[cn];
                g_logits[(size_t)m0 * VOCABn + cn]       = acc[mt][nt][0] + bb;
                g_logits[(size_t)(m0 + 8) * VOCABn + cn] = acc[mt][nt][2] + bb;
            }
            if (cn + 1 < VOCABn) {
                float bb = linb[cn + 1];
                g_logits[(size_t)m0 * VOCABn + cn + 1]       = acc[mt][nt][1] + bb;
                g_logits[(size_t)(m0 + 8) * VOCABn + cn + 1] = acc[mt][nt][3] + bb;
            }
        }
    }
}

// =====================================================================
// Fused relu + log_softmax per decoder step, one block per row.
// =====================================================================
__global__ void __launch_bounds__(512)
softmax_kernel(float* __restrict__ out)
{
    __shared__ float red[16];
    const int t = blockIdx.x;
    const float* row = g_logits + (size_t)t * VOCABn;
    const int tid = threadIdx.x, lane = tid & 31, wid = tid >> 5;

    float m = 0.f;   // relu floor
    for (int i = tid; i < VOCABn; i += 512) m = fmaxf(m, row[i]);
    #pragma unroll
    for (int o = 16; o; o >>= 1) m = fmaxf(m, __shfl_xor_sync(0xffffffffu, m, o));
    if (lane == 0) red[wid] = m;
    __syncthreads();
    if (tid < 16) {
        float v = red[tid];
        #pragma unroll
        for (int o = 8; o; o >>= 1) v = fmaxf(v, __shfl_xor_sync(0x0000ffffu, v, o));
        if (tid == 0) red[0] = v;
    }
    __syncthreads();
    m = red[0];
    __syncthreads();

    float s = 0.f;
    for (int i = tid; i < VOCABn; i += 512) s += expf(fmaxf(row[i], 0.f) - m);
    #pragma unroll
    for (int o = 16; o; o >>= 1) s += __shfl_xor_sync(0xffffffffu, s, o);
    if (lane == 0) red[wid] = s;
    __syncthreads();
    if (tid < 16) {
        float v = red[tid];
        #pragma unroll
        for (int o = 8; o; o >>= 1) v += __shfl_xor_sync(0x0000ffffu, v, o);
        if (tid == 0) red[0] = v;
    }
    __syncthreads();
    const float lse = m + logf(red[0]);

    float* orow = out + (size_t)t * VOCABn;
    for (int i = tid; i < VOCABn; i += 512) orow[i] = fmaxf(row[i], 0.f) - lse;
}

// =====================================================================
extern "C" void kernel_launch(void* const* d_in, const int* in_sizes, int n_in,
                              void* d_out, int out_size)
{
    const int*   in_seq  = (const int*)d_in[0];
    const float* feats   = (const float*)d_in[1];
    const int*   dec_seq = (const int*)d_in[2];
    const float* emb     = (const float*)d_in[3];
    const float* eWih    = (const float*)d_in[4];
    const float* eWhh    = (const float*)d_in[5];
    const float* ebih    = (const float*)d_in[6];
    const float* ebhh    = (const float*)d_in[7];
    const float* dWih    = (const float*)d_in[8];
    const float* dWhh    = (const float*)d_in[9];
    const float* dbih    = (const float*)d_in[10];
    const float* dbhh    = (const float*)d_in[11];
    const float* linW    = (const float*)d_in[12];
    const float* linb    = (const float*)d_in[13];

    const size_t lstm_smem =
        (size_t)(RPBn * Hn + NSTEPn * RPBn + Hn + 2 * AEn + RPBn + UPBn + 4) * sizeof(float);

    cudaFuncSetAttribute(lstm_kernel, cudaFuncAttributeMaxDynamicSharedMemorySize,
                         (int)lstm_smem);
    cudaFuncSetAttribute(gemm_kernel, cudaFuncAttributeMaxDynamicSharedMemorySize,
                         GEMM_SMEM);

    lstm_kernel<<<NBLKn, NTHRn, lstm_smem>>>(in_seq, feats, dec_seq, emb,
                                             eWih, eWhh, ebih, ebhh,
                                             dWih, dWhh, dbih, dbhh);
    gemm_kernel<<<(VOCABn + GBN - 1) / GBN, 256, GEMM_SMEM>>>(linW, linb);
    softmax_kernel<<<SEQn, 512>>>((float*)d_out);
}

// round 4
// speedup vs baseline: 1.1776x; 1.0733x over previous
#include <cuda_runtime.h>
#include <cstdint>
#include <cstddef>

// ---------------- problem constants ----------------
#define Hn      1024
#define En      512
#define AEn     576
#define SEQn    64
#define NSTEPn  128
#define NBLKn   128
#define UPBn    8      // hidden units per block   (128*8 = 1024)
#define RPBn    32     // gate rows per block      (8 units * 4 gates)
#define NTHRn   512
#define VOCABn  50257

// ---------------- global scratch (no allocations allowed) ----------------
__device__ float    g_hbuf[2][Hn];          // double-buffered h broadcast
__device__ float    g_hs[SEQn * Hn];        // decoder hidden states
__device__ float    g_logits[SEQn * VOCABn];
__device__ unsigned g_epoch[NBLKn * 8];     // per-CTA epoch flags, 32B apart

__device__ __forceinline__ void st_release_u32(unsigned* p, unsigned v) {
    asm volatile("st.release.gpu.global.b32 [%0], %1;" :: "l"(p), "r"(v) : "memory");
}
__device__ __forceinline__ unsigned ld_acquire_u32(const unsigned* p) {
    unsigned v;
    asm volatile("ld.acquire.gpu.global.b32 %0, [%1];" : "=r"(v) : "l"(p) : "memory");
    return v;
}

// =====================================================================
// Persistent LSTM kernel: 128 CTAs, each owns 8 hidden units.
//  Phase A: precompute Gx[t][row] = x_t . Wih[row] + biases (local, x double-buffered)
//  Phase B: 128 timesteps synced via per-CTA epoch flags with HW
//           acquire/release, load-latency-paced polling (no nanosleep on the
//           hot path), and the remote gather overlapped with local gate math.
// =====================================================================
__global__ void __launch_bounds__(NTHRn, 1)
lstm_kernel(const int* __restrict__ in_seq, const float* __restrict__ feats,
            const int* __restrict__ dec_seq, const float* __restrict__ emb,
            const float* __restrict__ eWih, const float* __restrict__ eWhh,
            const float* __restrict__ ebih, const float* __restrict__ ebhh,
            const float* __restrict__ dWih, const float* __restrict__ dWhh,
            const float* __restrict__ dbih, const float* __restrict__ dbhh)
{
    extern __shared__ float sm[];
    float* w_s     = sm;                          // 32768 floats (32 rows x 1024)
    float* gx_s    = w_s + RPBn * Hn;             // 4096 floats (128 steps x 32 rows)
    float* h_s     = gx_s + NSTEPn * RPBn;        // 1024
    float* x_s     = h_s + Hn;                    // 2 x 576 (double buffer)
    float* gates_s = x_s + 2 * AEn;               // 32
    float* c_s     = gates_s + RPBn;              // 8
    unsigned* base_s = (unsigned*)(c_s + UPBn);   // 1

    const int tid  = threadIdx.x;
    const int lane = tid & 31;
    const int wid  = tid >> 5;
    const int blk  = blockIdx.x;

    if (tid == 0) base_s[0] = ld_acquire_u32(&g_epoch[blk * 8]);
    if (tid < UPBn) c_s[tid] = 0.f;
    for (int i = tid; i < Hn; i += NTHRn) h_s[i] = 0.f;

    // each warp handles two local gate rows: r_local = q*4 + gate
    const int r0 = 2 * wid, r1 = r0 + 1;
    const int grow0 = ((r0 & 3) << 10) + blk * UPBn + (r0 >> 2);
    const int grow1 = ((r1 & 3) << 10) + blk * UPBn + (r1 >> 2);

    // ---------------- Phase A1: encoder Gx (x double-buffered) ----------------
    {
        float4* dst = (float4*)w_s;
        for (int idx = tid; idx < RPBn * 128; idx += NTHRn) {   // 512 floats/row = 128 float4
            int r = idx >> 7, c4 = idx & 127;
            int gr = ((r & 3) << 10) + blk * UPBn + (r >> 2);
            dst[r * 128 + c4] = ((const float4*)eWih)[gr * 128 + c4];
        }
        float b0 = ebih[grow0] + ebhh[grow0];
        float b1 = ebih[grow1] + ebhh[grow1];
        const int tok0 = in_seq[0];
        x_s[tid] = emb[(size_t)tok0 * En + tid];
        __syncthreads();

        for (int t = 0; t < SEQn; t++) {
            const float* xc = x_s + (t & 1) * AEn;
            float* xn = x_s + ((t + 1) & 1) * AEn;
            float xnext = 0.f;
            const bool has = (t + 1 < SEQn);
            if (has) xnext = emb[(size_t)in_seq[t + 1] * En + tid];

            const float4* w0 = (const float4*)(w_s + r0 * En);
            const float4* w1 = (const float4*)(w_s + r1 * En);
            const float4* xp = (const float4*)xc;
            float a0 = 0.f, a1 = 0.f;
            #pragma unroll
            for (int k = 0; k < 4; k++) {
                int idx = k * 32 + lane;
                float4 xv = xp[idx];
                float4 v0 = w0[idx];
                float4 v1 = w1[idx];
                a0 = fmaf(xv.x, v0.x, fmaf(xv.y, v0.y, fmaf(xv.z, v0.z, fmaf(xv.w, v0.w, a0))));
                a1 = fmaf(xv.x, v1.x, fmaf(xv.y, v1.y, fmaf(xv.z, v1.z, fmaf(xv.w, v1.w, a1))));
            }
            #pragma unroll
            for (int o = 16; o; o >>= 1) {
                a0 += __shfl_xor_sync(0xffffffffu, a0, o);
                a1 += __shfl_xor_sync(0xffffffffu, a1, o);
            }
            if (lane == 0) { gx_s[t * RPBn + r0] = a0 + b0; gx_s[t * RPBn + r1] = a1 + b1; }
            if (has) xn[tid] = xnext;
            __syncthreads();
        }
    }

    // ---------------- Phase A2: decoder Gx ----------------
    {
        float4* dst = (float4*)w_s;
        for (int idx = tid; idx < RPBn * 144; idx += NTHRn) {   // 576 floats/row = 144 float4
            int r = idx / 144, c4 = idx % 144;
            int gr = ((r & 3) << 10) + blk * UPBn + (r >> 2);
            dst[r * 144 + c4] = ((const float4*)dWih)[gr * 144 + c4];
        }
        float b0 = dbih[grow0] + dbhh[grow0];
        float b1 = dbih[grow1] + dbhh[grow1];
        // feats tail: constant across steps -> preload both buffers
        if (tid < AEn - En) {
            float fv = feats[tid];
            x_s[En + tid] = fv;
            x_s[AEn + En + tid] = fv;
        }
        const int tok0 = dec_seq[0];
        x_s[tid] = emb[(size_t)tok0 * En + tid];
        __syncthreads();

        for (int t = 0; t < SEQn; t++) {
            const float* xc = x_s + (t & 1) * AEn;
            float* xn = x_s + ((t + 1) & 1) * AEn;
            float xnext = 0.f;
            const bool has = (t + 1 < SEQn);
            if (has) xnext = emb[(size_t)dec_seq[t + 1] * En + tid];

            const float4* w0 = (const float4*)(w_s + r0 * AEn);
            const float4* w1 = (const float4*)(w_s + r1 * AEn);
            const float4* xp = (const float4*)xc;
            float a0 = 0.f, a1 = 0.f;
            #pragma unroll
            for (int k = 0; k < 5; k++) {
                int idx = k * 32 + lane;
                if (idx < 144) {
                    float4 xv = xp[idx];
                    float4 v0 = w0[idx];
                    float4 v1 = w1[idx];
                    a0 = fmaf(xv.x, v0.x, fmaf(xv.y, v0.y, fmaf(xv.z, v0.z, fmaf(xv.w, v0.w, a0))));
                    a1 = fmaf(xv.x, v1.x, fmaf(xv.y, v1.y, fmaf(xv.z, v1.z, fmaf(xv.w, v1.w, a1))));
                }
            }
            #pragma unroll
            for (int o = 16; o; o >>= 1) {
                a0 += __shfl_xor_sync(0xffffffffu, a0, o);
                a1 += __shfl_xor_sync(0xffffffffu, a1, o);
            }
            if (lane == 0) {
                gx_s[(SEQn + t) * RPBn + r0] = a0 + b0;
                gx_s[(SEQn + t) * RPBn + r1] = a1 + b1;
            }
            if (has) xn[tid] = xnext;
            __syncthreads();
        }
    }

    // ---------------- Phase B: recurrent loop ----------------
    {
        float4* dst = (float4*)w_s;
        for (int idx = tid; idx < RPBn * 256; idx += NTHRn) {   // 1024 floats/row = 256 float4
            int r = idx >> 8, c4 = idx & 255;
            int gr = ((r & 3) << 10) + blk * UPBn + (r >> 2);
            dst[r * 256 + c4] = ((const float4*)eWhh)[gr * 256 + c4];
        }
    }
    __syncthreads();
    const unsigned base = base_s[0];

    const float4* wr0 = (const float4*)(w_s + r0 * Hn);
    const float4* wr1 = (const float4*)(w_s + r1 * Hn);

    for (int t = 0; t < NSTEPn; t++) {
        if (t == SEQn) {
            // swap in decoder Whh slice (all reads of enc slice are done)
            float4* dst = (float4*)w_s;
            for (int idx = tid; idx < RPBn * 256; idx += NTHRn) {
                int r = idx >> 8, c4 = idx & 255;
                int gr = ((r & 3) << 10) + blk * UPBn + (r >> 2);
                dst[r * 256 + c4] = ((const float4*)dWhh)[gr * 256 + c4];
            }
            __syncthreads();
        }

        // ---- Whh . h (each warp: 2 gate rows) ----
        const float4* hp = (const float4*)h_s;
        float a0 = 0.f, a1 = 0.f;
        #pragma unroll
        for (int k = 0; k < 8; k++) {
            int idx = k * 32 + lane;
            float4 hv4 = hp[idx];
            float4 v0 = wr0[idx];
            float4 v1 = wr1[idx];
            a0 = fmaf(hv4.x, v0.x, fmaf(hv4.y, v0.y, fmaf(hv4.z, v0.z, fmaf(hv4.w, v0.w, a0))));
            a1 = fmaf(hv4.x, v1.x, fmaf(hv4.y, v1.y, fmaf(hv4.z, v1.z, fmaf(hv4.w, v1.w, a1))));
        }
        #pragma unroll
        for (int o = 16; o; o >>= 1) {
            a0 += __shfl_xor_sync(0xffffffffu, a0, o);
            a1 += __shfl_xor_sync(0xffffffffu, a1, o);
        }
        if (lane == 0) {
            gates_s[r0] = a0 + gx_s[t * RPBn + r0];
            gates_s[r1] = a1 + gx_s[t * RPBn + r1];
        }
        __syncthreads();   // (S1) gates ready; all h_s reads for this step done

        const unsigned target = base + (unsigned)t + 1u;

        if (wid == 0) {
            // ---- gate nonlinearity + publish (warp 0) ----
            float hv = 0.f;
            if (tid < UPBn) {
                int q = tid;
                float gi = gates_s[q * 4 + 0];
                float gf = gates_s[q * 4 + 1];
                float gg = gates_s[q * 4 + 2];
                float go = gates_s[q * 4 + 3];
                float si = 1.f / (1.f + expf(-gi));
                float sf = 1.f / (1.f + expf(-gf));
                float so = 1.f / (1.f + expf(-go));
                float c  = fmaf(sf, c_s[q], si * tanhf(gg));
                hv = so * tanhf(c);
                c_s[q] = c;
                if (t >= SEQn) g_hs[(t - SEQn) * Hn + blk * UPBn + q] = hv;
            }
            float v0 = __shfl_sync(0xffffffffu, hv, 0);
            float v1 = __shfl_sync(0xffffffffu, hv, 1);
            float v2 = __shfl_sync(0xffffffffu, hv, 2);
            float v3 = __shfl_sync(0xffffffffu, hv, 3);
            float v4 = __shfl_sync(0xffffffffu, hv, 4);
            float v5 = __shfl_sync(0xffffffffu, hv, 5);
            float v6 = __shfl_sync(0xffffffffu, hv, 6);
            float v7 = __shfl_sync(0xffffffffu, hv, 7);
            if (lane == 0) {
                float4* dp = (float4*)&g_hbuf[t & 1][blk * UPBn];
                __stcg(dp,     make_float4(v0, v1, v2, v3));
                __stcg(dp + 1, make_float4(v4, v5, v6, v7));
                // release: orders the h stores before the epoch tag
                st_release_u32(&g_epoch[blk * 8], target);
            }
        } else if (wid >= 4 && wid < 8) {
            // ---- consumers (warps 4-7): gather all producers' h while
            //      warp 0 is still doing gate math + publish ----
            const int p = tid - 128;   // producer CTA id, 0..127
            const unsigned* ep = &g_epoch[p * 8];
            if ((int)(ld_acquire_u32(ep) - target) < 0) {
                int spins = 0;
                while ((int)(ld_acquire_u32(ep) - target) < 0) {
                    if (++spins > 4096) { __nanosleep(100); spins = 0; }
                }
            }
            // acquire load above orders these payload reads
            float4 lo = __ldcg((const float4*)&g_hbuf[t & 1][p * UPBn]);
            float4 hi = __ldcg((const float4*)&g_hbuf[t & 1][p * UPBn + 4]);
            float4* hdst = (float4*)&h_s[p * UPBn];
            hdst[0] = lo;
            hdst[1] = hi;
        }
        __syncthreads();   // (S2) h_s holds h_{t+1}
    }
}

// =====================================================================
// Output GEMM via tf32 tensor cores:
//   logits[64, 50257] = hs[64,1024] @ linW[50257,1024]^T + b
// BM=64, BN=128, BK=32, 256 threads (8 warps, 2m x 4n), 2-stage cp.async.
// =====================================================================
#define GBM 64
#define GBN 128
#define GBK 32
#define LDT 40                       // padded floats per smem row
#define A_STAGE (GBM * LDT)          // 2560 floats
#define B_STAGE (GBN * LDT)          // 5120 floats
#define STAGEF  (A_STAGE + B_STAGE)  // 7680 floats
#define GEMM_SMEM (2 * STAGEF * 4)   // 61440 bytes

__device__ __forceinline__ void cp_async16(float* smem_dst, const void* gsrc) {
    uint32_t d = (uint32_t)__cvta_generic_to_shared(smem_dst);
    asm volatile("cp.async.cg.shared.global [%0], [%1], 16;\n" :: "r"(d), "l"(gsrc));
}
__device__ __forceinline__ void cp_async16z(float* smem_dst, const void* gsrc, int szbytes) {
    uint32_t d = (uint32_t)__cvta_generic_to_shared(smem_dst);
    asm volatile("cp.async.cg.shared.global [%0], [%1], 16, %2;\n" :: "r"(d), "l"(gsrc), "r"(szbytes));
}

__global__ void __launch_bounds__(256, 2)
gemm_kernel(const float* __restrict__ linW, const float* __restrict__ linb)
{
    extern __shared__ float smg[];
    const int tid  = threadIdx.x;
    const int n0   = blockIdx.x * GBN;
    const int warp = tid >> 5, lane = tid & 31;
    const int wm   = warp >> 2, wn = warp & 3;
    const int g    = lane >> 2, tg = lane & 3;

    float acc[2][4][4];
    #pragma unroll
    for (int i = 0; i < 2; i++)
        #pragma unroll
        for (int j = 0; j < 4; j++)
            #pragma unroll
            for (int k = 0; k < 4; k++) acc[i][j][k] = 0.f;

    // stage loader: A (64x32) + B (128x32), coalesced 16B cp.async
    auto issue_stage = [&](int k0, int s) {
        float* As = smg + s * STAGEF;
        float* Bs = As + A_STAGE;
        #pragma unroll
        for (int i = 0; i < 2; i++) {
            int idx = i * 256 + tid;
            int m = idx >> 3, kq = idx & 7;
            cp_async16(&As[m * LDT + kq * 4], &g_hs[m * Hn + k0 + kq * 4]);
        }
        #pragma unroll
        for (int i = 0; i < 4; i++) {
            int idx = i * 256 + tid;
            int n = idx >> 3, kq = idx & 7;
            int gn = n0 + n;
            int cgn = (gn < VOCABn) ? gn : (VOCABn - 1);
            int sz  = (gn < VOCABn) ? 16 : 0;
            cp_async16z(&Bs[n * LDT + kq * 4], &linW[(size_t)cgn * Hn + k0 + kq * 4], sz);
        }
        asm volatile("cp.async.commit_group;\n");
    };

    issue_stage(0, 0);
    const int NCH = Hn / GBK;   // 32
    for (int c = 0; c < NCH; c++) {
        int s = c & 1;
        if (c + 1 < NCH) {
            issue_stage((c + 1) * GBK, s ^ 1);
            asm volatile("cp.async.wait_group 1;\n");
        } else {
            asm volatile("cp.async.wait_group 0;\n");
        }
        __syncthreads();

        const float* As = smg + s * STAGEF;
        const float* Bs = As + A_STAGE;
        #pragma unroll
        for (int ks = 0; ks < 4; ks++) {
            const int kk = ks * 8;
            uint32_t a[2][4], b[4][2];
            #pragma unroll
            for (int mt = 0; mt < 2; mt++) {
                const float* ap = &As[(wm * 32 + mt * 16 + g) * LDT + kk + tg];
                a[mt][0] = __float_as_uint(ap[0]);
                a[mt][1] = __float_as_uint(ap[8 * LDT]);
                a[mt][2] = __float_as_uint(ap[4]);
                a[mt][3] = __float_as_uint(ap[8 * LDT + 4]);
            }
            #pragma unroll
            for (int nt = 0; nt < 4; nt++) {
                const float* bp = &Bs[(wn * 32 + nt * 8 + g) * LDT + kk + tg];
                b[nt][0] = __float_as_uint(bp[0]);
                b[nt][1] = __float_as_uint(bp[4]);
            }
            #pragma unroll
            for (int mt = 0; mt < 2; mt++)
                #pragma unroll
                for (int nt = 0; nt < 4; nt++) {
                    asm volatile(
                        "mma.sync.aligned.m16n8k8.row.col.f32.tf32.tf32.f32 "
                        "{%0,%1,%2,%3}, {%4,%5,%6,%7}, {%8,%9}, {%0,%1,%2,%3};\n"
                        : "+f"(acc[mt][nt][0]), "+f"(acc[mt][nt][1]),
                          "+f"(acc[mt][nt][2]), "+f"(acc[mt][nt][3])
                        : "r"(a[mt][0]), "r"(a[mt][1]), "r"(a[mt][2]), "r"(a[mt][3]),
                          "r"(b[nt][0]), "r"(b[nt][1]));
                }
        }
        __syncthreads();
    }

    // epilogue: add bias, write logits (scalar stores, rows have odd stride)
    #pragma unroll
    for (int mt = 0; mt < 2; mt++) {
        const int m0 = wm * 32 + mt * 16 + g;
        #pragma unroll
        for (int nt = 0; nt < 4; nt++) {
            const int cn = n0 + wn * 32 + nt * 8 + 2 * tg;
            if (cn < VOCABn) {
                float bb = linb[cn];
                g_logits[(size_t)m0 * VOCABn + cn]       = acc[mt][nt][0] + bb;
                g_logits[(size_t)(m0 + 8) * VOCABn + cn] = acc[mt][nt][2] + bb;
            }
            if (cn + 1 < VOCABn) {
                float bb = linb[cn + 1];
                g_logits[(size_t)m0 * VOCABn + cn + 1]       = acc[mt][nt][1] + bb;
                g_logits[(size_t)(m0 + 8) * VOCABn + cn + 1] = acc[mt][nt][3] + bb;
            }
        }
    }
}

// =====================================================================
// Fused relu + log_softmax per decoder step, one block per row.
// =====================================================================
__global__ void __launch_bounds__(512)
softmax_kernel(float* __restrict__ out)
{
    __shared__ float red[16];
    const int t = blockIdx.x;
    const float* row = g_logits + (size_t)t * VOCABn;
    const int tid = threadIdx.x, lane = tid & 31, wid = tid >> 5;

    float m = 0.f;   // relu floor
    for (int i = tid; i < VOCABn; i += 512) m = fmaxf(m, row[i]);
    #pragma unroll
    for (int o = 16; o; o >>= 1) m = fmaxf(m, __shfl_xor_sync(0xffffffffu, m, o));
    if (lane == 0) red[wid] = m;
    __syncthreads();
    if (tid < 16) {
        float v = red[tid];
        #pragma unroll
        for (int o = 8; o; o >>= 1) v = fmaxf(v, __shfl_xor_sync(0x0000ffffu, v, o));
        if (tid == 0) red[0] = v;
    }
    __syncthreads();
    m = red[0];
    __syncthreads();

    float s = 0.f;
    for (int i = tid; i < VOCABn; i += 512) s += expf(fmaxf(row[i], 0.f) - m);
    #pragma unroll
    for (int o = 16; o; o >>= 1) s += __shfl_xor_sync(0xffffffffu, s, o);
    if (lane == 0) red[wid] = s;
    __syncthreads();
    if (tid < 16) {
        float v = red[tid];
        #pragma unroll
        for (int o = 8; o; o >>= 1) v += __shfl_xor_sync(0x0000ffffu, v, o);
        if (tid == 0) red[0] = v;
    }
    __syncthreads();
    const float lse = m + logf(red[0]);

    float* orow = out + (size_t)t * VOCABn;
    for (int i = tid; i < VOCABn; i += 512) orow[i] = fmaxf(row[i], 0.f) - lse;
}

// =====================================================================
extern "C" void kernel_launch(void* const* d_in, const int* in_sizes, int n_in,
                              void* d_out, int out_size)
{
    const int*   in_seq  = (const int*)d_in[0];
    const float* feats   = (const float*)d_in[1];
    const int*   dec_seq = (const int*)d_in[2];
    const float* emb     = (const float*)d_in[3];
    const float* eWih    = (const float*)d_in[4];
    const float* eWhh    = (const float*)d_in[5];
    const float* ebih    = (const float*)d_in[6];
    const float* ebhh    = (const float*)d_in[7];
    const float* dWih    = (const float*)d_in[8];
    const float* dWhh    = (const float*)d_in[9];
    const float* dbih    = (const float*)d_in[10];
    const float* dbhh    = (const float*)d_in[11];
    const float* linW    = (const float*)d_in[12];
    const float* linb    = (const float*)d_in[13];

    const size_t lstm_smem =
        (size_t)(RPBn * Hn + NSTEPn * RPBn + Hn + 2 * AEn + RPBn + UPBn + 4) * sizeof(float);

    cudaFuncSetAttribute(lstm_kernel, cudaFuncAttributeMaxDynamicSharedMemorySize,
                         (int)lstm_smem);
    cudaFuncSetAttribute(gemm_kernel, cudaFuncAttributeMaxDynamicSharedMemorySize,
                         GEMM_SMEM);

    lstm_kernel<<<NBLKn, NTHRn, lstm_smem>>>(in_seq, feats, dec_seq, emb,
                                             eWih, eWhh, ebih, ebhh,
                                             dWih, dWhh, dbih, dbhh);
    gemm_kernel<<<(VOCABn + GBN - 1) / GBN, 256, GEMM_SMEM>>>(linW, linb);
    softmax_kernel<<<SEQn, 512>>>((float*)d_out);
}